// round 3
// baseline (speedup 1.0000x reference)
#include <cuda_runtime.h>
#include <cuda_bf16.h>

#define MAXN 65536
#define MAXE 1200000
#define MAXPG (1024*128)

// ---------------- scratch (static device globals; no allocation) ----------------
__device__ float g_xl[MAXN * 128];
__device__ float g_xr[MAXN * 128];
__device__ int   g_deg[MAXN];
__device__ int   g_off[MAXN + 1];
__device__ int   g_cur[MAXN];
__device__ int   g_esrc[MAXE];
__device__ float g_pooled[MAXPG];

// ---------------- init: zero degree + pooled ----------------
__global__ void init_kernel(int N, int PG) {
    int i = blockIdx.x * blockDim.x + threadIdx.x;
    if (i < N)  g_deg[i] = 0;
    if (i < PG) g_pooled[i] = 0.f;
}

// ---------------- transform: xl = x@Wl, xr = x@Wr (fused, 8-node batches) -------
// smem: W[128][256] (128KB) + xs[8][128] (4KB) + partial[4][8][64] float4 (32KB)
#define T_SMEM_FLOATS (128*256 + 8*128 + 4*8*64*4)
__global__ void __launch_bounds__(256, 1)
transform_kernel(const float* __restrict__ x,
                 const float* __restrict__ Wl,
                 const float* __restrict__ Wr,
                 int N) {
    extern __shared__ float smem[];
    float* Wsh     = smem;                 // 32768 floats
    float* xs      = Wsh + 128 * 256;      // 1024 floats
    float* partial = xs + 8 * 128;         // 8192 floats
    float4* Wsh4     = (float4*)Wsh;
    float4* xs4      = (float4*)xs;
    float4* partial4 = (float4*)partial;

    const int t  = threadIdx.x;            // 256 threads
    const int cs = t & 63;                 // column group (4 cols)
    const int ks = t >> 6;                 // k-split 0..3 (32 k each)

    // load W into smem: cols 0..127 = Wl, 128..255 = Wr
    for (int i = t; i < 128 * 128; i += 256) {
        int k = i >> 7, j = i & 127;
        Wsh[k * 256 + j]       = Wl[i];
        Wsh[k * 256 + 128 + j] = Wr[i];
    }

    const int nbatch = (N + 7) / 8;
    for (int batch = blockIdx.x; batch < nbatch; batch += gridDim.x) {
        const int node0 = batch * 8;
        __syncthreads();   // protect xs/partial from previous iteration readers
        // load 8 node rows of x
        #pragma unroll
        for (int r = 0; r < 4; r++) {
            int idx = r * 256 + t;          // 0..1023
            int n = idx >> 7, k = idx & 127;
            int node = node0 + n;
            xs[idx] = (node < N) ? x[node * 128 + k] : 0.f;
        }
        __syncthreads();

        float4 acc[8];
        #pragma unroll
        for (int u = 0; u < 8; u++) acc[u] = make_float4(0.f, 0.f, 0.f, 0.f);

        #pragma unroll
        for (int kq = 0; kq < 8; kq++) {
            const int kb = ks * 32 + kq * 4;
            float4 xv[8];
            #pragma unroll
            for (int u = 0; u < 8; u++) xv[u] = xs4[u * 32 + (kb >> 2)];
            #pragma unroll
            for (int j = 0; j < 4; j++) {
                float4 w4 = Wsh4[(kb + j) * 64 + cs];
                #pragma unroll
                for (int u = 0; u < 8; u++) {
                    float xk = (j == 0) ? xv[u].x : (j == 1) ? xv[u].y
                             : (j == 2) ? xv[u].z : xv[u].w;
                    acc[u].x = fmaf(xk, w4.x, acc[u].x);
                    acc[u].y = fmaf(xk, w4.y, acc[u].y);
                    acc[u].z = fmaf(xk, w4.z, acc[u].z);
                    acc[u].w = fmaf(xk, w4.w, acc[u].w);
                }
            }
        }
        // write k-split partials
        #pragma unroll
        for (int u = 0; u < 8; u++) partial4[(ks * 8 + u) * 64 + cs] = acc[u];
        __syncthreads();
        // reduce 4 k-splits, write xl/xr
        #pragma unroll
        for (int r = 0; r < 2; r++) {
            int task = r * 256 + t;         // 0..511
            int n = task >> 6, c = task & 63;
            float4 s0 = partial4[(0 * 8 + n) * 64 + c];
            float4 s1 = partial4[(1 * 8 + n) * 64 + c];
            float4 s2 = partial4[(2 * 8 + n) * 64 + c];
            float4 s3 = partial4[(3 * 8 + n) * 64 + c];
            float4 sum;
            sum.x = s0.x + s1.x + s2.x + s3.x;
            sum.y = s0.y + s1.y + s2.y + s3.y;
            sum.z = s0.z + s1.z + s2.z + s3.z;
            sum.w = s0.w + s1.w + s2.w + s3.w;
            int node = node0 + n;
            if (node < N) {
                int col = c * 4;
                if (col < 128) *(float4*)&g_xl[node * 128 + col] = sum;
                else           *(float4*)&g_xr[node * 128 + col - 128] = sum;
            }
        }
    }
}

// ---------------- CSR build (edge_index is int32: [2,E] row-major) -------------
__global__ void degree_kernel(const int* __restrict__ ei, int E, int N) {
    for (int e = blockIdx.x * blockDim.x + threadIdx.x; e < E;
         e += gridDim.x * blockDim.x) {
        int dst = __ldg(&ei[E + e]);
        if ((unsigned)dst < (unsigned)N) atomicAdd(&g_deg[dst], 1);
    }
}

__global__ void scan_kernel(int N) {
    __shared__ int sm[1024];
    const int t = threadIdx.x;
    int carry = 0;
    const int nchunks = (N + 1023) / 1024;
    for (int c = 0; c < nchunks; c++) {
        int idx = c * 1024 + t;
        int v = (idx < N) ? g_deg[idx] : 0;
        sm[t] = v;
        __syncthreads();
        int val = v;
        for (int ofs = 1; ofs < 1024; ofs <<= 1) {
            int other = (t >= ofs) ? sm[t - ofs] : 0;
            __syncthreads();
            val += other;
            sm[t] = val;
            __syncthreads();
        }
        int total = sm[1023];
        if (idx < N) {
            g_off[idx + 1] = carry + val;
            g_cur[idx]     = carry + val - v;
        }
        if (idx == 0) g_off[0] = 0;
        carry += total;
        __syncthreads();   // before next chunk overwrites sm
    }
}

__global__ void scatter_kernel(const int* __restrict__ ei, int E, int N) {
    for (int e = blockIdx.x * blockDim.x + threadIdx.x; e < E;
         e += gridDim.x * blockDim.x) {
        int srcv = __ldg(&ei[e]);
        int dst  = __ldg(&ei[E + e]);
        if ((unsigned)dst < (unsigned)N && (unsigned)srcv < (unsigned)N) {
            int pos = atomicAdd(&g_cur[dst], 1);
            g_esrc[pos] = srcv;
        }
    }
}

// ---------------- fused aggregation: online softmax + weighted sum + pool ------
#define NPW 8   // nodes per warp
__global__ void __launch_bounds__(256)
aggregate_kernel(const float* __restrict__ att,
                 const float* __restrict__ bias,
                 const int* __restrict__ batch_ids,
                 int N, int G) {
    const int warp = (blockIdx.x * blockDim.x + threadIdx.x) >> 5;
    const int lane = threadIdx.x & 31;
    const int node0 = warp * NPW;
    if (node0 >= N) return;

    const int h  = lane >> 3;      // head 0..3 (8 lanes per head)
    const int c0 = lane * 4;       // channel base in flat [H*C]=128
    const float4 attv  = *(const float4*)&att[h * 32 + (lane & 7) * 4];
    const float4 biasv = *(const float4*)&bias[c0];
    const float4* xp = (const float4*)g_xl;

    int cur_g = -1;
    float4 pmax = make_float4(0.f, 0.f, 0.f, 0.f);

    for (int i = 0; i < NPW; i++) {
        const int n = node0 + i;
        if (n >= N) break;
        const float4 xrv = *(const float4*)&g_xr[n * 128 + c0];
        const int beg = g_off[n];
        const int nE  = g_off[n + 1] - beg;

        float m = -1e30f, s = 0.f;
        float4 acc = make_float4(0.f, 0.f, 0.f, 0.f);

        // edge 0 = self loop (src = n), then CSR edges; prefetch one ahead
        float4 xl_nxt = xp[(size_t)n * 32 + lane];
        for (int j = 0; j <= nE; j++) {
            const float4 xlv = xl_nxt;
            if (j < nE) {
                int s2 = g_esrc[beg + j];
                xl_nxt = xp[(size_t)s2 * 32 + lane];
            }
            float ex = xlv.x + xrv.x; ex = ex > 0.f ? ex : 0.2f * ex;
            float ey = xlv.y + xrv.y; ey = ey > 0.f ? ey : 0.2f * ey;
            float ez = xlv.z + xrv.z; ez = ez > 0.f ? ez : 0.2f * ez;
            float ew = xlv.w + xrv.w; ew = ew > 0.f ? ew : 0.2f * ew;
            float tt = ex * attv.x + ey * attv.y + ez * attv.z + ew * attv.w;
            tt += __shfl_xor_sync(0xffffffffu, tt, 1);
            tt += __shfl_xor_sync(0xffffffffu, tt, 2);
            tt += __shfl_xor_sync(0xffffffffu, tt, 4);   // per-head logit

            float mn = fmaxf(m, tt);
            float sc = __expf(m - mn);
            float w  = __expf(tt - mn);
            s = s * sc + w;
            acc.x = acc.x * sc + w * xlv.x;
            acc.y = acc.y * sc + w * xlv.y;
            acc.z = acc.z * sc + w * xlv.z;
            acc.w = acc.w * sc + w * xlv.w;
            m = mn;
        }
        const float inv = 1.f / s;
        float4 o;
        o.x = fmaxf(acc.x * inv + biasv.x, 0.f);
        o.y = fmaxf(acc.y * inv + biasv.y, 0.f);
        o.z = fmaxf(acc.z * inv + biasv.z, 0.f);
        o.w = fmaxf(acc.w * inv + biasv.w, 0.f);

        int g = __ldg(&batch_ids[n]);
        if ((unsigned)g >= (unsigned)G) g = 0;
        if (g != cur_g) {
            if (cur_g >= 0) {
                int* pb = (int*)&g_pooled[cur_g * 128 + c0];
                atomicMax(pb + 0, __float_as_int(pmax.x));
                atomicMax(pb + 1, __float_as_int(pmax.y));
                atomicMax(pb + 2, __float_as_int(pmax.z));
                atomicMax(pb + 3, __float_as_int(pmax.w));
            }
            cur_g = g;
            pmax = o;
        } else {
            pmax.x = fmaxf(pmax.x, o.x);
            pmax.y = fmaxf(pmax.y, o.y);
            pmax.z = fmaxf(pmax.z, o.z);
            pmax.w = fmaxf(pmax.w, o.w);
        }
    }
    if (cur_g >= 0) {
        int* pb = (int*)&g_pooled[cur_g * 128 + c0];
        atomicMax(pb + 0, __float_as_int(pmax.x));
        atomicMax(pb + 1, __float_as_int(pmax.y));
        atomicMax(pb + 2, __float_as_int(pmax.z));
        atomicMax(pb + 3, __float_as_int(pmax.w));
    }
}

// ---------------- MLP head: out = relu(pooled @ W_mlp + b_mlp) ----------------
__global__ void mlp_kernel(const float* __restrict__ Wm,
                           const float* __restrict__ bm,
                           float* __restrict__ out, int G) {
    __shared__ float p[128];
    const int g = blockIdx.x;
    const int t = threadIdx.x;
    p[t] = g_pooled[g * 128 + t];
    __syncthreads();
    float acc = bm[t];
    #pragma unroll 8
    for (int k = 0; k < 128; k++) acc = fmaf(p[k], Wm[k * 128 + t], acc);
    out[g * 128 + t] = fmaxf(acc, 0.f);
}

// ---------------- launch ----------------
extern "C" void kernel_launch(void* const* d_in, const int* in_sizes, int n_in,
                              void* d_out, int out_size) {
    const float* x     = (const float*)d_in[0];
    const int*   ei    = (const int*)d_in[1];     // int32 (JAX x64 disabled)
    const int*   batch = (const int*)d_in[2];     // int32
    // d_in[3] = num_graphs (derived from out_size instead)
    const float* Wl    = (const float*)d_in[4];
    const float* Wr    = (const float*)d_in[5];
    const float* att   = (const float*)d_in[6];
    const float* bias  = (const float*)d_in[7];
    const float* Wm    = (const float*)d_in[8];
    const float* bm    = (const float*)d_in[9];
    float* out = (float*)d_out;

    const int N = in_sizes[0] / 128;
    const int E = in_sizes[1] / 2;
    const int G = out_size / 128;
    if (N > MAXN || E > MAXE || G * 128 > MAXPG) return;

    const int PG = G * 128;
    int initN = (N > PG) ? N : PG;
    init_kernel<<<(initN + 255) / 256, 256>>>(N, PG);

    const int tsmem = T_SMEM_FLOATS * sizeof(float);
    cudaFuncSetAttribute(transform_kernel,
                         cudaFuncAttributeMaxDynamicSharedMemorySize, tsmem);
    transform_kernel<<<148, 256, tsmem>>>(x, Wl, Wr, N);

    degree_kernel<<<1024, 256>>>(ei, E, N);
    scan_kernel<<<1, 1024>>>(N);
    scatter_kernel<<<1024, 256>>>(ei, E, N);

    aggregate_kernel<<<(N + NPW * 8 - 1) / (NPW * 8), 256>>>(att, bias, batch, N, G);

    mlp_kernel<<<G, 128>>>(Wm, bm, out, G);
}

// round 4
// speedup vs baseline: 1.2126x; 1.2126x over previous
#include <cuda_runtime.h>
#include <cuda_bf16.h>

#define MAXN 65536
#define MAXE 1200000
#define MAXPG (1024*128)
#define SCAN_B 1024
#define MAXNB (MAXN / SCAN_B)   // 64

// ---------------- scratch (static device globals; no allocation) ----------------
__device__ float g_xl[MAXN * 128];
__device__ float g_xr[MAXN * 128];
__device__ int   g_deg[MAXN];
__device__ int   g_off[MAXN + 1];
__device__ int   g_cur[MAXN];
__device__ int   g_esrc[MAXE];
__device__ float g_pooled[MAXPG];
__device__ int   g_bsum[MAXNB];
__device__ int   g_boff[MAXNB];

// ---------------- init: zero degree + pooled ----------------
__global__ void init_kernel(int N, int PG) {
    int i = blockIdx.x * blockDim.x + threadIdx.x;
    if (i < N)  g_deg[i] = 0;
    if (i < PG) g_pooled[i] = 0.f;
}

// ---------------- transform: xl = x@Wl, xr = x@Wr (fused, 8-node batches) -------
// smem: W[128][256] (128KB) + xs[8][128] (4KB) + partial[4][8][64] float4 (32KB)
#define T_SMEM_FLOATS (128*256 + 8*128 + 4*8*64*4)
__global__ void __launch_bounds__(256, 1)
transform_kernel(const float* __restrict__ x,
                 const float* __restrict__ Wl,
                 const float* __restrict__ Wr,
                 int N) {
    extern __shared__ float smem[];
    float* Wsh     = smem;                 // 32768 floats
    float* xs      = Wsh + 128 * 256;      // 1024 floats
    float* partial = xs + 8 * 128;         // 8192 floats
    float4* Wsh4     = (float4*)Wsh;
    float4* xs4      = (float4*)xs;
    float4* partial4 = (float4*)partial;

    const int t  = threadIdx.x;            // 256 threads
    const int cs = t & 63;                 // column group (4 cols)
    const int ks = t >> 6;                 // k-split 0..3 (32 k each)

    // load W into smem: cols 0..127 = Wl, 128..255 = Wr
    for (int i = t; i < 128 * 128; i += 256) {
        int k = i >> 7, j = i & 127;
        Wsh[k * 256 + j]       = Wl[i];
        Wsh[k * 256 + 128 + j] = Wr[i];
    }

    const int nbatch = (N + 7) / 8;
    for (int batch = blockIdx.x; batch < nbatch; batch += gridDim.x) {
        const int node0 = batch * 8;
        __syncthreads();   // protect xs/partial from previous iteration readers
        // load 8 node rows of x
        #pragma unroll
        for (int r = 0; r < 4; r++) {
            int idx = r * 256 + t;          // 0..1023
            int n = idx >> 7, k = idx & 127;
            int node = node0 + n;
            xs[idx] = (node < N) ? x[node * 128 + k] : 0.f;
        }
        __syncthreads();

        float4 acc[8];
        #pragma unroll
        for (int u = 0; u < 8; u++) acc[u] = make_float4(0.f, 0.f, 0.f, 0.f);

        #pragma unroll
        for (int kq = 0; kq < 8; kq++) {
            const int kb = ks * 32 + kq * 4;
            float4 xv[8];
            #pragma unroll
            for (int u = 0; u < 8; u++) xv[u] = xs4[u * 32 + (kb >> 2)];
            #pragma unroll
            for (int j = 0; j < 4; j++) {
                float4 w4 = Wsh4[(kb + j) * 64 + cs];
                #pragma unroll
                for (int u = 0; u < 8; u++) {
                    float xk = (j == 0) ? xv[u].x : (j == 1) ? xv[u].y
                             : (j == 2) ? xv[u].z : xv[u].w;
                    acc[u].x = fmaf(xk, w4.x, acc[u].x);
                    acc[u].y = fmaf(xk, w4.y, acc[u].y);
                    acc[u].z = fmaf(xk, w4.z, acc[u].z);
                    acc[u].w = fmaf(xk, w4.w, acc[u].w);
                }
            }
        }
        // write k-split partials
        #pragma unroll
        for (int u = 0; u < 8; u++) partial4[(ks * 8 + u) * 64 + cs] = acc[u];
        __syncthreads();
        // reduce 4 k-splits, write xl/xr
        #pragma unroll
        for (int r = 0; r < 2; r++) {
            int task = r * 256 + t;         // 0..511
            int n = task >> 6, c = task & 63;
            float4 s0 = partial4[(0 * 8 + n) * 64 + c];
            float4 s1 = partial4[(1 * 8 + n) * 64 + c];
            float4 s2 = partial4[(2 * 8 + n) * 64 + c];
            float4 s3 = partial4[(3 * 8 + n) * 64 + c];
            float4 sum;
            sum.x = s0.x + s1.x + s2.x + s3.x;
            sum.y = s0.y + s1.y + s2.y + s3.y;
            sum.z = s0.z + s1.z + s2.z + s3.z;
            sum.w = s0.w + s1.w + s2.w + s3.w;
            int node = node0 + n;
            if (node < N) {
                int col = c * 4;
                if (col < 128) *(float4*)&g_xl[node * 128 + col] = sum;
                else           *(float4*)&g_xr[node * 128 + col - 128] = sum;
            }
        }
    }
}

// ---------------- CSR build (edge_index is int32: [2,E] row-major) -------------
__global__ void degree_kernel(const int* __restrict__ ei, int E, int N) {
    for (int e = blockIdx.x * blockDim.x + threadIdx.x; e < E;
         e += gridDim.x * blockDim.x) {
        int dst = __ldg(&ei[E + e]);
        if ((unsigned)dst < (unsigned)N) atomicAdd(&g_deg[dst], 1);
    }
}

// -------- chip-wide exclusive scan of g_deg -> g_off/g_cur (3 small kernels) ----
__global__ void block_sum_kernel(int N) {          // grid = nb, block = 1024
    const int t = threadIdx.x;
    const int idx = blockIdx.x * SCAN_B + t;
    int v = (idx < N) ? g_deg[idx] : 0;
    // warp reduce
    int s = v;
    #pragma unroll
    for (int o = 16; o > 0; o >>= 1) s += __shfl_xor_sync(0xffffffffu, s, o);
    __shared__ int wsum[32];
    if ((t & 31) == 0) wsum[t >> 5] = s;
    __syncthreads();
    if (t < 32) {
        int w = wsum[t];
        #pragma unroll
        for (int o = 16; o > 0; o >>= 1) w += __shfl_xor_sync(0xffffffffu, w, o);
        if (t == 0) g_bsum[blockIdx.x] = w;
    }
}

__global__ void bsum_scan_kernel(int nb) {         // 1 block, 1 warp
    if (threadIdx.x == 0) {
        int c = 0;
        for (int i = 0; i < nb; i++) { g_boff[i] = c; c += g_bsum[i]; }
    }
}

__global__ void scan_final_kernel(int N) {         // grid = nb, block = 1024
    const int t = threadIdx.x;
    const int lane = t & 31, wid = t >> 5;
    const int idx = blockIdx.x * SCAN_B + t;
    int v = (idx < N) ? g_deg[idx] : 0;
    // inclusive warp scan
    int val = v;
    #pragma unroll
    for (int o = 1; o < 32; o <<= 1) {
        int n = __shfl_up_sync(0xffffffffu, val, o);
        if (lane >= o) val += n;
    }
    __shared__ int wsum[32];
    if (lane == 31) wsum[wid] = val;
    __syncthreads();
    if (wid == 0) {
        int w = (t < 32) ? wsum[t] : 0;
        #pragma unroll
        for (int o = 1; o < 32; o <<= 1) {
            int n = __shfl_up_sync(0xffffffffu, w, o);
            if (lane >= o) w += n;
        }
        wsum[t] = w;
    }
    __syncthreads();
    int incl = val + (wid > 0 ? wsum[wid - 1] : 0) + g_boff[blockIdx.x];
    if (idx < N) {
        g_off[idx + 1] = incl;
        g_cur[idx]     = incl - v;
    }
    if (idx == 0) g_off[0] = 0;
}

__global__ void scatter_kernel(const int* __restrict__ ei, int E, int N) {
    for (int e = blockIdx.x * blockDim.x + threadIdx.x; e < E;
         e += gridDim.x * blockDim.x) {
        int srcv = __ldg(&ei[e]);
        int dst  = __ldg(&ei[E + e]);
        if ((unsigned)dst < (unsigned)N && (unsigned)srcv < (unsigned)N) {
            int pos = atomicAdd(&g_cur[dst], 1);
            g_esrc[pos] = srcv;
        }
    }
}

// ---------------- fused aggregation: online softmax + weighted sum + pool ------
#define NPW 8   // nodes per warp
__global__ void __launch_bounds__(256)
aggregate_kernel(const float* __restrict__ att,
                 const float* __restrict__ bias,
                 const int* __restrict__ batch_ids,
                 int N, int G) {
    const int warp = (blockIdx.x * blockDim.x + threadIdx.x) >> 5;
    const int lane = threadIdx.x & 31;
    const int node0 = warp * NPW;
    if (node0 >= N) return;

    const int h  = lane >> 3;      // head 0..3 (8 lanes per head)
    const int c0 = lane * 4;       // channel base in flat [H*C]=128
    const float4 attv  = *(const float4*)&att[h * 32 + (lane & 7) * 4];
    const float4 biasv = *(const float4*)&bias[c0];
    const float4* xp = (const float4*)g_xl;

    int cur_g = -1;
    float4 pmax = make_float4(0.f, 0.f, 0.f, 0.f);

    for (int i = 0; i < NPW; i++) {
        const int n = node0 + i;
        if (n >= N) break;
        const float4 xrv = *(const float4*)&g_xr[n * 128 + c0];
        const int beg = g_off[n];
        const int nE  = g_off[n + 1] - beg;

        float m = -1e30f, s = 0.f;
        float4 acc = make_float4(0.f, 0.f, 0.f, 0.f);

        // edge 0 = self loop (src = n), then CSR edges; prefetch one ahead
        float4 xl_nxt = xp[(size_t)n * 32 + lane];
        for (int j = 0; j <= nE; j++) {
            const float4 xlv = xl_nxt;
            if (j < nE) {
                int s2 = g_esrc[beg + j];
                xl_nxt = xp[(size_t)s2 * 32 + lane];
            }
            float ex = xlv.x + xrv.x; ex = ex > 0.f ? ex : 0.2f * ex;
            float ey = xlv.y + xrv.y; ey = ey > 0.f ? ey : 0.2f * ey;
            float ez = xlv.z + xrv.z; ez = ez > 0.f ? ez : 0.2f * ez;
            float ew = xlv.w + xrv.w; ew = ew > 0.f ? ew : 0.2f * ew;
            float tt = ex * attv.x + ey * attv.y + ez * attv.z + ew * attv.w;
            tt += __shfl_xor_sync(0xffffffffu, tt, 1);
            tt += __shfl_xor_sync(0xffffffffu, tt, 2);
            tt += __shfl_xor_sync(0xffffffffu, tt, 4);   // per-head logit

            float mn = fmaxf(m, tt);
            float sc = __expf(m - mn);
            float w  = __expf(tt - mn);
            s = s * sc + w;
            acc.x = acc.x * sc + w * xlv.x;
            acc.y = acc.y * sc + w * xlv.y;
            acc.z = acc.z * sc + w * xlv.z;
            acc.w = acc.w * sc + w * xlv.w;
            m = mn;
        }
        const float inv = 1.f / s;
        float4 o;
        o.x = fmaxf(acc.x * inv + biasv.x, 0.f);
        o.y = fmaxf(acc.y * inv + biasv.y, 0.f);
        o.z = fmaxf(acc.z * inv + biasv.z, 0.f);
        o.w = fmaxf(acc.w * inv + biasv.w, 0.f);

        int g = __ldg(&batch_ids[n]);
        if ((unsigned)g >= (unsigned)G) g = 0;
        if (g != cur_g) {
            if (cur_g >= 0) {
                int* pb = (int*)&g_pooled[cur_g * 128 + c0];
                atomicMax(pb + 0, __float_as_int(pmax.x));
                atomicMax(pb + 1, __float_as_int(pmax.y));
                atomicMax(pb + 2, __float_as_int(pmax.z));
                atomicMax(pb + 3, __float_as_int(pmax.w));
            }
            cur_g = g;
            pmax = o;
        } else {
            pmax.x = fmaxf(pmax.x, o.x);
            pmax.y = fmaxf(pmax.y, o.y);
            pmax.z = fmaxf(pmax.z, o.z);
            pmax.w = fmaxf(pmax.w, o.w);
        }
    }
    if (cur_g >= 0) {
        int* pb = (int*)&g_pooled[cur_g * 128 + c0];
        atomicMax(pb + 0, __float_as_int(pmax.x));
        atomicMax(pb + 1, __float_as_int(pmax.y));
        atomicMax(pb + 2, __float_as_int(pmax.z));
        atomicMax(pb + 3, __float_as_int(pmax.w));
    }
}

// ---------------- MLP head: out = relu(pooled @ W_mlp + b_mlp) ----------------
__global__ void mlp_kernel(const float* __restrict__ Wm,
                           const float* __restrict__ bm,
                           float* __restrict__ out, int G) {
    __shared__ float p[128];
    const int g = blockIdx.x;
    const int t = threadIdx.x;
    p[t] = g_pooled[g * 128 + t];
    __syncthreads();
    float acc = bm[t];
    #pragma unroll 8
    for (int k = 0; k < 128; k++) acc = fmaf(p[k], Wm[k * 128 + t], acc);
    out[g * 128 + t] = fmaxf(acc, 0.f);
}

// ---------------- launch ----------------
extern "C" void kernel_launch(void* const* d_in, const int* in_sizes, int n_in,
                              void* d_out, int out_size) {
    const float* x     = (const float*)d_in[0];
    const int*   ei    = (const int*)d_in[1];     // int32 (JAX x64 disabled)
    const int*   batch = (const int*)d_in[2];     // int32
    // d_in[3] = num_graphs (derived from out_size instead)
    const float* Wl    = (const float*)d_in[4];
    const float* Wr    = (const float*)d_in[5];
    const float* att   = (const float*)d_in[6];
    const float* bias  = (const float*)d_in[7];
    const float* Wm    = (const float*)d_in[8];
    const float* bm    = (const float*)d_in[9];
    float* out = (float*)d_out;

    const int N = in_sizes[0] / 128;
    const int E = in_sizes[1] / 2;
    const int G = out_size / 128;
    if (N > MAXN || E > MAXE || G * 128 > MAXPG) return;

    const int PG = G * 128;
    int initN = (N > PG) ? N : PG;
    init_kernel<<<(initN + 255) / 256, 256>>>(N, PG);

    const int tsmem = T_SMEM_FLOATS * sizeof(float);
    cudaFuncSetAttribute(transform_kernel,
                         cudaFuncAttributeMaxDynamicSharedMemorySize, tsmem);
    transform_kernel<<<148, 256, tsmem>>>(x, Wl, Wr, N);

    degree_kernel<<<1024, 256>>>(ei, E, N);

    const int nb = (N + SCAN_B - 1) / SCAN_B;
    block_sum_kernel<<<nb, SCAN_B>>>(N);
    bsum_scan_kernel<<<1, 32>>>(nb);
    scan_final_kernel<<<nb, SCAN_B>>>(N);

    scatter_kernel<<<1024, 256>>>(ei, E, N);

    aggregate_kernel<<<(N + NPW * 8 - 1) / (NPW * 8), 256>>>(att, bias, batch, N, G);

    mlp_kernel<<<G, 128>>>(Wm, bm, out, G);
}